// round 12
// baseline (speedup 1.0000x reference)
#include <cuda_runtime.h>
#include <cuda_fp16.h>
#include <math.h>
#include <stdint.h>

#define Bb 16
#define Tt 2048
#define Hh 512
#define Kk 15
#define BT (Bb*Tt)

// ---- GEMM tiling ----
#define GM 128
#define GN 128
#define KC 16
#define NCHUNK (Hh/KC)
#define S3 3
#define WPR 12
#define BUFW (GM*WPR)
#define STGB (BUFW*4)
#define OFF_AH 0
#define OFF_AL (S3*BUFW)
#define OFF_BH (2*S3*BUFW)
#define OFF_BL (3*S3*BUFW)
#define SMEM_GEMM (4*S3*BUFW*4)   // 73728

#define CORR_SCALE 2048.0f
#define CORR_INV   (1.0f/2048.0f)

// ---- conv tiling ----
#define CT 32
#define SMEM_CONV ((CT*Hh + 3*Hh)*4)   // 71680

// ---------------- scratch ----------------
__device__ float d_g[(size_t)BT*Hh];
__device__ __align__(16) __half d_xh[(size_t)BT*Hh];
__device__ __align__(16) __half d_xl[(size_t)BT*Hh];   // residual * 2048
__device__ __align__(16) __half d_wh[1024*Hh];
__device__ __align__(16) __half d_wl[1024*Hh];         // residual * 2048
__device__ float d_alphas[BT];
__device__ float d_weff[Hh];
__device__ float d_wpart[16*Hh];
__device__ float d_beff;
__device__ int   d_nfires[Bb];
__device__ int   d_fire_t[BT];
__device__ float d_dist[BT];
__device__ float d_remain[BT];
__device__ float d_ptn[Bb];

__device__ __forceinline__ float sigm(float v){ return 1.0f/(1.0f + expf(-v)); }

__device__ __forceinline__ float bfred(float v){
    #pragma unroll
    for (int o = 16; o > 0; o >>= 1) v += __shfl_xor_sync(0xffffffffu, v, o);
    return v;
}

// hi = rn16(v), lo = rn16((v - hi) * 2048): scaled residual keeps fp16-normal range
__device__ __forceinline__ void pack4s(const float4& v, uint32_t& hw0, uint32_t& hw1,
                                       uint32_t& lw0, uint32_t& lw1){
    __half hx = __float2half_rn(v.x), hy = __float2half_rn(v.y);
    __half hz = __float2half_rn(v.z), hq = __float2half_rn(v.w);
    __half lx = __float2half_rn((v.x - __half2float(hx))*CORR_SCALE);
    __half ly = __float2half_rn((v.y - __half2float(hy))*CORR_SCALE);
    __half lz = __float2half_rn((v.z - __half2float(hz))*CORR_SCALE);
    __half lq = __float2half_rn((v.w - __half2float(hq))*CORR_SCALE);
    __half2 a = __halves2half2(hx,hy); hw0 = *(uint32_t*)&a;
    __half2 b = __halves2half2(hz,hq); hw1 = *(uint32_t*)&b;
    __half2 c = __halves2half2(lx,ly); lw0 = *(uint32_t*)&c;
    __half2 d = __halves2half2(lz,lq); lw1 = *(uint32_t*)&d;
}

// main product: f32 accumulate
__device__ __forceinline__ void mma_f16(float* c, const uint32_t* a, const uint32_t* b){
    asm volatile(
        "mma.sync.aligned.m16n8k16.row.col.f32.f16.f16.f32 "
        "{%0,%1,%2,%3}, {%4,%5,%6,%7}, {%8,%9}, {%0,%1,%2,%3};"
        : "+f"(c[0]), "+f"(c[1]), "+f"(c[2]), "+f"(c[3])
        : "r"(a[0]), "r"(a[1]), "r"(a[2]), "r"(a[3]), "r"(b[0]), "r"(b[1]));
}
// correction products: f16 accumulate (2 packed half2 regs)
__device__ __forceinline__ void mma_f16acc(uint32_t* c, const uint32_t* a, const uint32_t* b){
    asm volatile(
        "mma.sync.aligned.m16n8k16.row.col.f16.f16.f16.f16 "
        "{%0,%1}, {%2,%3,%4,%5}, {%6,%7}, {%0,%1};"
        : "+r"(c[0]), "+r"(c[1])
        : "r"(a[0]), "r"(a[1]), "r"(a[2]), "r"(a[3]), "r"(b[0]), "r"(b[1]));
}

__device__ __forceinline__ uint32_t smem_u32(const void* p){
    uint32_t a;
    asm("{ .reg .u64 t; cvta.to.shared.u64 t, %1; cvt.u32.u64 %0, t; }" : "=r"(a) : "l"(p));
    return a;
}
__device__ __forceinline__ void cp16(uint32_t dst, const void* src){
    asm volatile("cp.async.cg.shared.global [%0], [%1], 16;"
                 :: "r"(dst), "l"(__cvta_generic_to_global(src)) : "memory");
}
#define CP_COMMIT() asm volatile("cp.async.commit_group;" ::: "memory")
#define CP_WAIT(n)  asm volatile("cp.async.wait_group %0;" :: "n"(n) : "memory")

// ---------------- pre-split kernels ----------------
__global__ void presplit_x(const float* __restrict__ x)
{
    size_t i = (size_t)blockIdx.x*256 + threadIdx.x;
    float4 v = ((const float4*)x)[i];
    uint32_t h0,h1,l0,l1;
    pack4s(v, h0,h1,l0,l1);
    ((uint2*)d_xh)[i] = make_uint2(h0,h1);
    ((uint2*)d_xl)[i] = make_uint2(l0,l1);
}
__global__ void presplit_w(const float* __restrict__ w)
{
    int i = blockIdx.x*256 + threadIdx.x;
    int nq = i >> 7, kq = i & 127;
    int wr = (nq >> 1) + (nq & 1)*Hh;
    float4 v = *(const float4*)(w + (size_t)wr*Hh + kq*4);
    uint32_t h0,h1,l0,l1;
    pack4s(v, h0,h1,l0,l1);
    size_t o = (size_t)nq*128 + kq;
    ((uint2*)d_wh)[o] = make_uint2(h0,h1);
    ((uint2*)d_wl)[o] = make_uint2(l0,l1);
}

// ---------------- weff ----------------
__global__ void weff_part(const float* __restrict__ pw2_w, const float* __restrict__ lin_w)
{
    int t = threadIdx.x, j = blockIdx.x;
    float s = 0.0f;
    #pragma unroll
    for (int o = j*32; o < j*32 + 32; o++)
        s = fmaf(lin_w[o], pw2_w[(size_t)o*Hh + t], s);
    d_wpart[j*Hh + t] = s;
}
__global__ void weff_sum(const float* __restrict__ pw2_b, const float* __restrict__ lin_w,
                         const float* __restrict__ lin_b)
{
    __shared__ float red[16];
    int t = threadIdx.x;
    float s = 0.0f;
    #pragma unroll
    for (int j = 0; j < 16; j++) s += d_wpart[j*Hh + t];
    d_weff[t] = s;
    float p = lin_w[t] * pw2_b[t];
    p = bfred(p);
    if ((t & 31) == 0) red[t >> 5] = p;
    __syncthreads();
    if (t == 0) {
        float bb = lin_b[0];
        #pragma unroll
        for (int i = 0; i < 16; i++) bb += red[i];
        d_beff = bb;
    }
}

// ---------------- kernel 1: fp16 GEMM, f32-acc main + f16-acc scaled corrections ----------------
__global__ void __launch_bounds__(256)
gemm_glu_mma(const float* __restrict__ bias)
{
    extern __shared__ uint32_t smg[];
    const uint32_t sm0 = smem_u32(smg);

    const int tid  = threadIdx.x;
    const int wid  = tid >> 5;
    const int lane = tid & 31;
    const int gid  = lane >> 2;
    const int tig  = lane & 3;
    const int mB = blockIdx.y * GM;
    const int nB = blockIdx.x * GN;
    const int cB = nB >> 1;
    const int mw = (wid & 3) * 32;
    const int nw = (wid >> 2) * 64;

    const int r_  = tid >> 1;
    const int hq_ = tid & 1;
    const uint32_t dA0 = sm0 + (uint32_t)(r_*WPR)*4 + hq_*16;
    const size_t   ga0 = ((size_t)(mB + r_)*Hh)*2 + hq_*16;
    const size_t   gb0 = ((size_t)(nB + r_)*Hh)*2 + hq_*16;

    #define ISSUE(c) do { \
        const int st_ = (c) % S3; \
        const size_t kb_ = (size_t)(c)*KC*2; \
        cp16(dA0 + (OFF_AH*4) + st_*STGB, (const char*)d_xh + ga0 + kb_); \
        cp16(dA0 + (OFF_AL*4) + st_*STGB, (const char*)d_xl + ga0 + kb_); \
        cp16(dA0 + (OFF_BH*4) + st_*STGB, (const char*)d_wh + gb0 + kb_); \
        cp16(dA0 + (OFF_BL*4) + st_*STGB, (const char*)d_wl + gb0 + kb_); \
        CP_COMMIT(); \
    } while(0)

    float acc[2][8][4];
    uint32_t corr[2][8][2];
    #pragma unroll
    for (int mt = 0; mt < 2; mt++)
        #pragma unroll
        for (int nt = 0; nt < 8; nt++) {
            #pragma unroll
            for (int e = 0; e < 4; e++) acc[mt][nt][e] = 0.0f;
            corr[mt][nt][0] = 0u; corr[mt][nt][1] = 0u;
        }

    #define COMPUTE(buf) do { \
        const uint32_t* AHp = smg + OFF_AH + (buf)*BUFW + mw*WPR; \
        const uint32_t* ALp = smg + OFF_AL + (buf)*BUFW + mw*WPR; \
        const uint32_t* BHp = smg + OFF_BH + (buf)*BUFW + nw*WPR; \
        const uint32_t* BLp = smg + OFF_BL + (buf)*BUFW + nw*WPR; \
        uint32_t ah[2][4], al[2][4]; \
        _Pragma("unroll") \
        for (int mt = 0; mt < 2; mt++) { \
            const int r0 = (mt*16 + gid)*WPR; \
            ah[mt][0] = AHp[r0 + tig];           al[mt][0] = ALp[r0 + tig]; \
            ah[mt][1] = AHp[r0 + 8*WPR + tig];   al[mt][1] = ALp[r0 + 8*WPR + tig]; \
            ah[mt][2] = AHp[r0 + tig + 4];       al[mt][2] = ALp[r0 + tig + 4]; \
            ah[mt][3] = AHp[r0 + 8*WPR + tig+4]; al[mt][3] = ALp[r0 + 8*WPR + tig+4]; \
        } \
        _Pragma("unroll") \
        for (int ng = 0; ng < 2; ng++) { \
            uint32_t bh[4][2], bl[4][2]; \
            _Pragma("unroll") \
            for (int nt = 0; nt < 4; nt++) { \
                const int n = ((ng*4 + nt)*8 + gid)*WPR; \
                bh[nt][0] = BHp[n + tig];     bl[nt][0] = BLp[n + tig]; \
                bh[nt][1] = BHp[n + tig + 4]; bl[nt][1] = BLp[n + tig + 4]; \
            } \
            _Pragma("unroll") \
            for (int nt = 0; nt < 4; nt++) { \
                mma_f16(acc[0][ng*4+nt], ah[0], bh[nt]); \
                mma_f16(acc[1][ng*4+nt], ah[1], bh[nt]); \
            } \
            _Pragma("unroll") \
            for (int nt = 0; nt < 4; nt++) { \
                mma_f16acc(corr[0][ng*4+nt], ah[0], bl[nt]); \
                mma_f16acc(corr[1][ng*4+nt], ah[1], bl[nt]); \
            } \
            _Pragma("unroll") \
            for (int nt = 0; nt < 4; nt++) { \
                mma_f16acc(corr[0][ng*4+nt], al[0], bh[nt]); \
                mma_f16acc(corr[1][ng*4+nt], al[1], bh[nt]); \
            } \
        } \
    } while(0)

    ISSUE(0);
    ISSUE(1);

    #pragma unroll 1
    for (int c = 0; c < NCHUNK; c++) {
        if (c < NCHUNK - 1) { CP_WAIT(1); } else { CP_WAIT(0); }
        __syncthreads();
        COMPUTE(c % S3);
        if (c + 2 < NCHUNK) ISSUE(c + 2);
    }

    // ---- epilogue: merge scaled corrections, GLU on (even,odd) col pairs ----
    #pragma unroll
    for (int nt = 0; nt < 8; nt++) {
        const int ch = cB + (nw >> 1) + nt*4 + tig;
        const float bv = bias[ch];
        const float bg = bias[Hh + ch];
        #pragma unroll
        for (int mt = 0; mt < 2; mt++) {
            const int m0 = mB + mw + mt*16 + gid;
            float2 c01 = __half22float2(*(const __half2*)&corr[mt][nt][0]);
            float2 c23 = __half22float2(*(const __half2*)&corr[mt][nt][1]);
            float v0 = fmaf(c01.x, CORR_INV, acc[mt][nt][0]);
            float v1 = fmaf(c01.y, CORR_INV, acc[mt][nt][1]);
            float v2 = fmaf(c23.x, CORR_INV, acc[mt][nt][2]);
            float v3 = fmaf(c23.y, CORR_INV, acc[mt][nt][3]);
            float g0 = (v0 + bv) * sigm(v1 + bg);
            float g2 = (v2 + bv) * sigm(v3 + bg);
            d_g[(size_t)m0*Hh + ch]       = g0;
            d_g[(size_t)(m0 + 8)*Hh + ch] = g2;
        }
    }
}

// ---------------- kernel 2: conv + LN + swish -> alphas ----------------
__global__ void __launch_bounds__(512, 2)
conv_ln_logit2(const float* __restrict__ dw_w, const float* __restrict__ dw_b,
               const float* __restrict__ ln_g, const float* __restrict__ ln_b,
               const int* __restrict__ x_lens)
{
    extern __shared__ float smc[];
    float* cs = smc;
    float* pg = smc + CT*Hh;
    float* pb = pg + Hh;
    float* pw = pb + Hh;

    const int ch = threadIdx.x;
    const int b  = blockIdx.y;
    const int t0 = blockIdx.x * CT;
    const int lane = ch & 31;
    const int wrp  = ch >> 5;

    {
        float wk[15];
        #pragma unroll
        for (int k = 0; k < 15; k++) wk[k] = dw_w[ch*Kk + k];
        const float bias = dw_b[ch];
        const float* gb = d_g + (size_t)b*Tt*Hh + ch;

        float win[15];
        #pragma unroll
        for (int k = 0; k < 14; k++) {
            int tg = t0 - 14 + k;
            win[k] = (tg >= 0) ? gb[(size_t)tg*Hh] : 0.0f;
        }
        #pragma unroll
        for (int t = 0; t < CT; t++) {
            win[(t+14)%15] = gb[(size_t)(t0 + t)*Hh];
            float c = bias;
            #pragma unroll
            for (int k = 0; k < 15; k++) c = fmaf(win[(t+k)%15], wk[k], c);
            cs[t*Hh + ch] = c;
        }
        pg[ch] = ln_g[ch];
        pb[ch] = ln_b[ch];
        pw[ch] = d_weff[ch];
    }
    __syncthreads();

    const int len  = x_lens[b];
    const float beff = d_beff;
    #pragma unroll
    for (int rep = 0; rep < 2; rep++) {
        const int t = wrp*2 + rep;
        const float* cr = cs + t*Hh + lane*4;
        float4 c4[4];
        #pragma unroll
        for (int q = 0; q < 4; q++) c4[q] = *(const float4*)(cr + q*128);

        float s1 = 0.0f, s2 = 0.0f;
        #pragma unroll
        for (int q = 0; q < 4; q++) {
            const float* cp = (const float*)&c4[q];
            #pragma unroll
            for (int e = 0; e < 4; e++) { s1 += cp[e]; s2 = fmaf(cp[e], cp[e], s2); }
        }
        s1 = bfred(s1);
        s2 = bfred(s2);
        float mean = s1 * (1.0f/512.0f);
        float var  = s2 * (1.0f/512.0f) - mean*mean;
        float rstd = rsqrtf(var + 1e-5f);

        float dot = 0.0f;
        #pragma unroll
        for (int q = 0; q < 4; q++) {
            float4 g4 = *(const float4*)(pg + lane*4 + q*128);
            float4 b4 = *(const float4*)(pb + lane*4 + q*128);
            float4 w4 = *(const float4*)(pw + lane*4 + q*128);
            const float* cp = (const float*)&c4[q];
            const float* gp = (const float*)&g4;
            const float* bp = (const float*)&b4;
            const float* wp = (const float*)&w4;
            #pragma unroll
            for (int e = 0; e < 4; e++) {
                float y  = (cp[e] - mean) * rstd * gp[e] + bp[e];
                float sw = y * sigm(y);
                dot = fmaf(sw, wp[e], dot);
            }
        }
        dot = bfred(dot);
        if (lane == 0) {
            int tg = t0 + t;
            d_alphas[b*Tt + tg] = (tg < len) ? sigm(dot + beff) : 0.0f;
        }
    }
}

// ---------------- kernel 3: per-batch serial CIF scan ----------------
__global__ void scan_kernel()
{
    __shared__ float sa[Tt];
    const int b = blockIdx.x;
    for (int i = threadIdx.x; i < Tt; i += blockDim.x) sa[i] = d_alphas[b*Tt + i];
    __syncthreads();
    if (threadIdx.x == 0) {
        float integ = 0.0f, psum = 0.0f;
        int j = 0;
        for (int t = 0; t < Tt; t++) {
            float a = sa[t];
            psum += a;
            float tt = integ + a;
            bool fire = (tt >= 1.0f);
            if (fire) {
                float dist = 1.0f - integ;
                d_fire_t[b*Tt + j] = t;
                d_dist  [b*Tt + j] = dist;
                d_remain[b*Tt + j] = a - dist;
                j++;
            }
            integ = fire ? (tt - 1.0f) : tt;
        }
        d_nfires[b] = j;
        d_ptn[b] = psum;
    }
}

// ---------------- kernel 4: write all outputs ----------------
__launch_bounds__(128)
__global__ void output_kernel(const float* __restrict__ x, float* __restrict__ out)
{
    const int b   = blockIdx.y;
    const int j   = blockIdx.x;
    const int tid = threadIdx.x;
    float* outF = out;
    float* outP = out + (size_t)Bb*Tt*Hh;
    float* outR = outP + Bb;

    if (j == 0 && tid == 0) outP[b] = d_ptn[b];

    float4 acc = make_float4(0.0f, 0.0f, 0.0f, 0.0f);
    const int nf = d_nfires[b];

    if (j < nf) {
        const float* xb = x + (size_t)b*Tt*Hh + tid*4;
        const int tEnd = d_fire_t[b*Tt + j];
        int t;
        if (j > 0) {
            int   tPrev = d_fire_t[b*Tt + j - 1];
            float wl    = d_remain[b*Tt + j - 1];
            float4 v = *(const float4*)(xb + (size_t)tPrev*Hh);
            acc.x = wl*v.x; acc.y = wl*v.y; acc.z = wl*v.z; acc.w = wl*v.w;
            t = tPrev + 1;
        } else {
            t = 0;
        }
        for (; t < tEnd; t++) {
            float w = d_alphas[b*Tt + t];
            float4 v = *(const float4*)(xb + (size_t)t*Hh);
            acc.x = fmaf(w, v.x, acc.x); acc.y = fmaf(w, v.y, acc.y);
            acc.z = fmaf(w, v.z, acc.z); acc.w = fmaf(w, v.w, acc.w);
        }
        float wd = d_dist[b*Tt + j];
        float4 v = *(const float4*)(xb + (size_t)tEnd*Hh);
        acc.x = fmaf(wd, v.x, acc.x); acc.y = fmaf(wd, v.y, acc.y);
        acc.z = fmaf(wd, v.z, acc.z); acc.w = fmaf(wd, v.w, acc.w);
    }

    *(float4*)(outF + ((size_t)b*Tt + j)*Hh + tid*4) = acc;
    *(float4*)(outR + ((size_t)b*Tt + j)*Hh + (Hh - 4 - tid*4)) =
        make_float4(acc.w, acc.z, acc.y, acc.x);
}

// ---------------- launch ----------------
extern "C" void kernel_launch(void* const* d_in, const int* in_sizes, int n_in,
                              void* d_out, int out_size)
{
    const float* x      = (const float*)d_in[0];
    const int*   x_lens = (const int*)  d_in[1];
    const float* pw1_w  = (const float*)d_in[2];
    const float* pw1_b  = (const float*)d_in[3];
    const float* dw_w   = (const float*)d_in[4];
    const float* dw_b   = (const float*)d_in[5];
    const float* ln_g   = (const float*)d_in[6];
    const float* ln_b   = (const float*)d_in[7];
    const float* pw2_w  = (const float*)d_in[8];
    const float* pw2_b  = (const float*)d_in[9];
    const float* lin_w  = (const float*)d_in[10];
    const float* lin_b  = (const float*)d_in[11];
    float* out = (float*)d_out;

    cudaFuncSetAttribute(gemm_glu_mma,   cudaFuncAttributeMaxDynamicSharedMemorySize, SMEM_GEMM);
    cudaFuncSetAttribute(conv_ln_logit2, cudaFuncAttributeMaxDynamicSharedMemorySize, SMEM_CONV);

    presplit_x<<<(BT*Hh/4)/256, 256>>>(x);
    presplit_w<<<(1024*128)/256, 256>>>(pw1_w);
    weff_part<<<16, Hh>>>(pw2_w, lin_w);
    weff_sum<<<1, Hh>>>(pw2_b, lin_w, lin_b);
    gemm_glu_mma<<<dim3(8, BT/GM), 256, SMEM_GEMM>>>(pw1_b);
    conv_ln_logit2<<<dim3(Tt/CT, Bb), Hh, SMEM_CONV>>>(dw_w, dw_b, ln_g, ln_b, x_lens);
    scan_kernel<<<Bb, 256>>>();
    output_kernel<<<dim3(Tt, Bb), 128>>>(x, out);
}

// round 13
// speedup vs baseline: 1.1762x; 1.1762x over previous
#include <cuda_runtime.h>
#include <cuda_fp16.h>
#include <math.h>
#include <stdint.h>

#define Bb 16
#define Tt 2048
#define Hh 512
#define Kk 15
#define BT (Bb*Tt)

// ---- GEMM tiling ----
#define GM 128
#define GN 128
#define KC 16
#define NCHUNK (Hh/KC)
#define S3 3
#define WPR 12
#define BUFW (GM*WPR)
#define STGB (BUFW*4)
#define OFF_AH 0
#define OFF_AL (S3*BUFW)
#define OFF_BH (2*S3*BUFW)
#define OFF_BL (3*S3*BUFW)
#define SMEM_GEMM (4*S3*BUFW*4)   // 73728 -> 2 blocks/SM

// ---- conv tiling ----
#define CT 32
#define SMEM_CONV ((CT*Hh + 3*Hh)*4)   // 71680

// ---------------- scratch ----------------
__device__ float d_g[(size_t)BT*Hh];
__device__ __align__(16) __half d_wh[1024*Hh];   // interleaved weights hi
__device__ __align__(16) __half d_wl[1024*Hh];   // interleaved weights lo
__device__ float d_alphas[BT];
__device__ float d_weff[Hh];
__device__ float d_wpart[16*Hh];
__device__ float d_beff;
__device__ int   d_nfires[Bb];
__device__ int   d_fire_t[BT];
__device__ float d_dist[BT];
__device__ float d_remain[BT];
__device__ float d_ptn[Bb];

__device__ __forceinline__ float sigm(float v){ return 1.0f/(1.0f + expf(-v)); }

__device__ __forceinline__ float bfred(float v){
    #pragma unroll
    for (int o = 16; o > 0; o >>= 1) v += __shfl_xor_sync(0xffffffffu, v, o);
    return v;
}

// fp16 hi/lo split (11+11 mantissa bits ~ tf32x3 accuracy), unscaled residual (R11 semantics)
__device__ __forceinline__ void h_split(float v, __half& h, __half& l){
    h = __float2half_rn(v);
    l = __float2half_rn(v - __half2float(h));
}
__device__ __forceinline__ void pack4(const float4& v, uint32_t& hw0, uint32_t& hw1,
                                      uint32_t& lw0, uint32_t& lw1){
    __half hx,lx,hy,ly,hz,lz,hq,lq;
    h_split(v.x,hx,lx); h_split(v.y,hy,ly); h_split(v.z,hz,lz); h_split(v.w,hq,lq);
    __half2 a = __halves2half2(hx,hy); hw0 = *(uint32_t*)&a;
    __half2 b = __halves2half2(hz,hq); hw1 = *(uint32_t*)&b;
    __half2 c = __halves2half2(lx,ly); lw0 = *(uint32_t*)&c;
    __half2 d = __halves2half2(lz,lq); lw1 = *(uint32_t*)&d;
}

__device__ __forceinline__ void mma_f16(float* c, const uint32_t* a, const uint32_t* b){
    asm volatile(
        "mma.sync.aligned.m16n8k16.row.col.f32.f16.f16.f32 "
        "{%0,%1,%2,%3}, {%4,%5,%6,%7}, {%8,%9}, {%0,%1,%2,%3};"
        : "+f"(c[0]), "+f"(c[1]), "+f"(c[2]), "+f"(c[3])
        : "r"(a[0]), "r"(a[1]), "r"(a[2]), "r"(a[3]), "r"(b[0]), "r"(b[1]));
}

__device__ __forceinline__ uint32_t smem_u32(const void* p){
    uint32_t a;
    asm("{ .reg .u64 t; cvta.to.shared.u64 t, %1; cvt.u32.u64 %0, t; }" : "=r"(a) : "l"(p));
    return a;
}
__device__ __forceinline__ void cp16(uint32_t dst, const void* src){
    asm volatile("cp.async.cg.shared.global [%0], [%1], 16;"
                 :: "r"(dst), "l"(__cvta_generic_to_global(src)) : "memory");
}
#define CP_COMMIT() asm volatile("cp.async.commit_group;" ::: "memory")
#define CP_WAIT(n)  asm volatile("cp.async.wait_group %0;" :: "n"(n) : "memory")

// ---------------- pre-split: weights only (x split lives in the GEMM producer) ----------------
__global__ void presplit_w(const float* __restrict__ w)
{
    int i = blockIdx.x*256 + threadIdx.x;
    int nq = i >> 7, kq = i & 127;
    int wr = (nq >> 1) + (nq & 1)*Hh;       // even=value row c, odd=gate row c+H
    float4 v = *(const float4*)(w + (size_t)wr*Hh + kq*4);
    uint32_t h0,h1,l0,l1;
    pack4(v, h0,h1,l0,l1);
    size_t o = (size_t)nq*128 + kq;
    ((uint2*)d_wh)[o] = make_uint2(h0,h1);
    ((uint2*)d_wl)[o] = make_uint2(l0,l1);
}

// ---------------- weff ----------------
__global__ void weff_part(const float* __restrict__ pw2_w, const float* __restrict__ lin_w)
{
    int t = threadIdx.x, j = blockIdx.x;
    float s = 0.0f;
    #pragma unroll
    for (int o = j*32; o < j*32 + 32; o++)
        s = fmaf(lin_w[o], pw2_w[(size_t)o*Hh + t], s);
    d_wpart[j*Hh + t] = s;
}
__global__ void weff_sum(const float* __restrict__ pw2_b, const float* __restrict__ lin_w,
                         const float* __restrict__ lin_b)
{
    __shared__ float red[16];
    int t = threadIdx.x;
    float s = 0.0f;
    #pragma unroll
    for (int j = 0; j < 16; j++) s += d_wpart[j*Hh + t];
    d_weff[t] = s;
    float p = lin_w[t] * pw2_b[t];
    p = bfred(p);
    if ((t & 31) == 0) red[t >> 5] = p;
    __syncthreads();
    if (t == 0) {
        float bb = lin_b[0];
        #pragma unroll
        for (int i = 0; i < 16; i++) bb += red[i];
        d_beff = bb;
    }
}

// ---------------- kernel 1: fp16x3 mma.sync GEMM + GLU ----------------
// A: LDG f32 -> in-producer hi/lo split -> STS (double-buffered regs).
// B: cp.async from pre-split halves, 2 chunks in flight.
__global__ void __launch_bounds__(256, 2)
gemm_glu_mma(const float* __restrict__ x, const float* __restrict__ bias)
{
    extern __shared__ uint32_t smg[];
    const uint32_t sm0 = smem_u32(smg);

    const int tid  = threadIdx.x;
    const int wid  = tid >> 5;
    const int lane = tid & 31;
    const int gid  = lane >> 2;
    const int tig  = lane & 3;
    const int mB = blockIdx.y * GM;
    const int nB = blockIdx.x * GN;
    const int cB = nB >> 1;
    const int mw = (wid & 3) * 32;
    const int nw = (wid >> 2) * 64;

    // producer mapping: r_ = row 0..127, hq_ = which 8-K half of the 16-K chunk
    const int r_  = tid >> 1;
    const int hq_ = tid & 1;
    const uint32_t dOff = (uint32_t)(r_*WPR)*4 + hq_*16;   // byte offset within a stage buffer
    const float*  gax = x + (size_t)(mB + r_)*Hh + hq_*8;  // A source (f32)
    const size_t  gb0 = ((size_t)(nB + r_)*Hh)*2 + hq_*16; // B source (bytes into half arrays)

    // B-only async issue
    #define ISSUEB(c) do { \
        const int st_ = (c) % S3; \
        const size_t kb_ = (size_t)(c)*KC*2; \
        cp16(sm0 + (OFF_BH*4) + st_*STGB + dOff, (const char*)d_wh + gb0 + kb_); \
        cp16(sm0 + (OFF_BL*4) + st_*STGB + dOff, (const char*)d_wl + gb0 + kb_); \
        CP_COMMIT(); \
    } while(0)

    float4 xa0, xa1;   // staged A (8 floats)
    #define LDGA(c) do { \
        xa0 = *(const float4*)(gax + (size_t)(c)*KC); \
        xa1 = *(const float4*)(gax + (size_t)(c)*KC + 4); \
    } while(0)

    #define STSA(c) do { \
        const int st_ = (c) % S3; \
        uint32_t h0,h1,h2,h3,l0,l1,l2,l3; \
        pack4(xa0, h0,h1,l0,l1); \
        pack4(xa1, h2,h3,l2,l3); \
        *(uint4*)((char*)smg + (OFF_AH*4) + st_*STGB + dOff) = make_uint4(h0,h1,h2,h3); \
        *(uint4*)((char*)smg + (OFF_AL*4) + st_*STGB + dOff) = make_uint4(l0,l1,l2,l3); \
    } while(0)

    float acc[2][8][4];
    #pragma unroll
    for (int mt = 0; mt < 2; mt++)
        #pragma unroll
        for (int nt = 0; nt < 8; nt++)
            #pragma unroll
            for (int e = 0; e < 4; e++) acc[mt][nt][e] = 0.0f;

    #define COMPUTE(buf) do { \
        const uint32_t* AHp = smg + OFF_AH + (buf)*BUFW + mw*WPR; \
        const uint32_t* ALp = smg + OFF_AL + (buf)*BUFW + mw*WPR; \
        const uint32_t* BHp = smg + OFF_BH + (buf)*BUFW + nw*WPR; \
        const uint32_t* BLp = smg + OFF_BL + (buf)*BUFW + nw*WPR; \
        uint32_t ah[2][4], al[2][4]; \
        _Pragma("unroll") \
        for (int mt = 0; mt < 2; mt++) { \
            const int r0 = (mt*16 + gid)*WPR; \
            ah[mt][0] = AHp[r0 + tig];           al[mt][0] = ALp[r0 + tig]; \
            ah[mt][1] = AHp[r0 + 8*WPR + tig];   al[mt][1] = ALp[r0 + 8*WPR + tig]; \
            ah[mt][2] = AHp[r0 + tig + 4];       al[mt][2] = ALp[r0 + tig + 4]; \
            ah[mt][3] = AHp[r0 + 8*WPR + tig+4]; al[mt][3] = ALp[r0 + 8*WPR + tig+4]; \
        } \
        _Pragma("unroll") \
        for (int ng = 0; ng < 2; ng++) { \
            uint32_t bh[4][2], bl[4][2]; \
            _Pragma("unroll") \
            for (int nt = 0; nt < 4; nt++) { \
                const int n = ((ng*4 + nt)*8 + gid)*WPR; \
                bh[nt][0] = BHp[n + tig];     bl[nt][0] = BLp[n + tig]; \
                bh[nt][1] = BHp[n + tig + 4]; bl[nt][1] = BLp[n + tig + 4]; \
            } \
            _Pragma("unroll") \
            for (int nt = 0; nt < 4; nt++) { \
                mma_f16(acc[0][ng*4+nt], ah[0], bh[nt]); \
                mma_f16(acc[1][ng*4+nt], ah[1], bh[nt]); \
            } \
            _Pragma("unroll") \
            for (int nt = 0; nt < 4; nt++) { \
                mma_f16(acc[0][ng*4+nt], ah[0], bl[nt]); \
                mma_f16(acc[1][ng*4+nt], ah[1], bl[nt]); \
            } \
            _Pragma("unroll") \
            for (int nt = 0; nt < 4; nt++) { \
                mma_f16(acc[0][ng*4+nt], al[0], bh[nt]); \
                mma_f16(acc[1][ng*4+nt], al[1], bh[nt]); \
            } \
        } \
    } while(0)

    // prologue: A chunk 0 staged; B chunks 0,1 in flight
    ISSUEB(0);
    ISSUEB(1);
    LDGA(0);
    STSA(0);

    #pragma unroll 1
    for (int c = 0; c < NCHUNK; c++) {
        if (c + 1 < NCHUNK) LDGA(c + 1);          // prefetch A into regs
        if (c < NCHUNK - 1) { CP_WAIT(1); } else { CP_WAIT(0); }
        __syncthreads();                          // stage c ready (A stored last iter, B arrived)
        COMPUTE(c % S3);
        if (c + 2 < NCHUNK) ISSUEB(c + 2);
        __syncthreads();                          // all warps done with stage (c+1)%S3's old data
        if (c + 1 < NCHUNK) STSA(c + 1);
    }

    // ---- epilogue: GLU on (even,odd) col pairs -> d_g ----
    #pragma unroll
    for (int nt = 0; nt < 8; nt++) {
        const int ch = cB + (nw >> 1) + nt*4 + tig;
        const float bv = bias[ch];
        const float bg = bias[Hh + ch];
        #pragma unroll
        for (int mt = 0; mt < 2; mt++) {
            const int m0 = mB + mw + mt*16 + gid;
            float g0 = (acc[mt][nt][0] + bv) * sigm(acc[mt][nt][1] + bg);
            float g2 = (acc[mt][nt][2] + bv) * sigm(acc[mt][nt][3] + bg);
            d_g[(size_t)m0*Hh + ch]       = g0;
            d_g[(size_t)(m0 + 8)*Hh + ch] = g2;
        }
    }
}

// ---------------- kernel 2: conv + LN + swish -> alphas ----------------
__global__ void __launch_bounds__(512, 2)
conv_ln_logit2(const float* __restrict__ dw_w, const float* __restrict__ dw_b,
               const float* __restrict__ ln_g, const float* __restrict__ ln_b,
               const int* __restrict__ x_lens)
{
    extern __shared__ float smc[];
    float* cs = smc;
    float* pg = smc + CT*Hh;
    float* pb = pg + Hh;
    float* pw = pb + Hh;

    const int ch = threadIdx.x;
    const int b  = blockIdx.y;
    const int t0 = blockIdx.x * CT;
    const int lane = ch & 31;
    const int wrp  = ch >> 5;

    {
        float wk[15];
        #pragma unroll
        for (int k = 0; k < 15; k++) wk[k] = dw_w[ch*Kk + k];
        const float bias = dw_b[ch];
        const float* gb = d_g + (size_t)b*Tt*Hh + ch;

        float win[15];
        #pragma unroll
        for (int k = 0; k < 14; k++) {
            int tg = t0 - 14 + k;
            win[k] = (tg >= 0) ? gb[(size_t)tg*Hh] : 0.0f;
        }
        #pragma unroll
        for (int t = 0; t < CT; t++) {
            win[(t+14)%15] = gb[(size_t)(t0 + t)*Hh];
            float c = bias;
            #pragma unroll
            for (int k = 0; k < 15; k++) c = fmaf(win[(t+k)%15], wk[k], c);
            cs[t*Hh + ch] = c;
        }
        pg[ch] = ln_g[ch];
        pb[ch] = ln_b[ch];
        pw[ch] = d_weff[ch];
    }
    __syncthreads();

    const int len  = x_lens[b];
    const float beff = d_beff;
    #pragma unroll
    for (int rep = 0; rep < 2; rep++) {
        const int t = wrp*2 + rep;
        const float* cr = cs + t*Hh + lane*4;
        float4 c4[4];
        #pragma unroll
        for (int q = 0; q < 4; q++) c4[q] = *(const float4*)(cr + q*128);

        float s1 = 0.0f, s2 = 0.0f;
        #pragma unroll
        for (int q = 0; q < 4; q++) {
            const float* cp = (const float*)&c4[q];
            #pragma unroll
            for (int e = 0; e < 4; e++) { s1 += cp[e]; s2 = fmaf(cp[e], cp[e], s2); }
        }
        s1 = bfred(s1);
        s2 = bfred(s2);
        float mean = s1 * (1.0f/512.0f);
        float var  = s2 * (1.0f/512.0f) - mean*mean;
        float rstd = rsqrtf(var + 1e-5f);

        float dot = 0.0f;
        #pragma unroll
        for (int q = 0; q < 4; q++) {
            float4 g4 = *(const float4*)(pg + lane*4 + q*128);
            float4 b4 = *(const float4*)(pb + lane*4 + q*128);
            float4 w4 = *(const float4*)(pw + lane*4 + q*128);
            const float* cp = (const float*)&c4[q];
            const float* gp = (const float*)&g4;
            const float* bp = (const float*)&b4;
            const float* wp = (const float*)&w4;
            #pragma unroll
            for (int e = 0; e < 4; e++) {
                float y  = (cp[e] - mean) * rstd * gp[e] + bp[e];
                float sw = y * sigm(y);
                dot = fmaf(sw, wp[e], dot);
            }
        }
        dot = bfred(dot);
        if (lane == 0) {
            int tg = t0 + t;
            d_alphas[b*Tt + tg] = (tg < len) ? sigm(dot + beff) : 0.0f;
        }
    }
}

// ---------------- kernel 3: per-batch serial CIF scan ----------------
__global__ void scan_kernel()
{
    __shared__ float sa[Tt];
    const int b = blockIdx.x;
    for (int i = threadIdx.x; i < Tt; i += blockDim.x) sa[i] = d_alphas[b*Tt + i];
    __syncthreads();
    if (threadIdx.x == 0) {
        float integ = 0.0f, psum = 0.0f;
        int j = 0;
        for (int t = 0; t < Tt; t++) {
            float a = sa[t];
            psum += a;
            float tt = integ + a;
            bool fire = (tt >= 1.0f);
            if (fire) {
                float dist = 1.0f - integ;
                d_fire_t[b*Tt + j] = t;
                d_dist  [b*Tt + j] = dist;
                d_remain[b*Tt + j] = a - dist;
                j++;
            }
            integ = fire ? (tt - 1.0f) : tt;
        }
        d_nfires[b] = j;
        d_ptn[b] = psum;
    }
}

// ---------------- kernel 4: write all outputs ----------------
__launch_bounds__(128)
__global__ void output_kernel(const float* __restrict__ x, float* __restrict__ out)
{
    const int b   = blockIdx.y;
    const int j   = blockIdx.x;
    const int tid = threadIdx.x;
    float* outF = out;
    float* outP = out + (size_t)Bb*Tt*Hh;
    float* outR = outP + Bb;

    if (j == 0 && tid == 0) outP[b] = d_ptn[b];

    float4 acc = make_float4(0.0f, 0.0f, 0.0f, 0.0f);
    const int nf = d_nfires[b];

    if (j < nf) {
        const float* xb = x + (size_t)b*Tt*Hh + tid*4;
        const int tEnd = d_fire_t[b*Tt + j];
        int t;
        if (j > 0) {
            int   tPrev = d_fire_t[b*Tt + j - 1];
            float wl    = d_remain[b*Tt + j - 1];
            float4 v = *(const float4*)(xb + (size_t)tPrev*Hh);
            acc.x = wl*v.x; acc.y = wl*v.y; acc.z = wl*v.z; acc.w = wl*v.w;
            t = tPrev + 1;
        } else {
            t = 0;
        }
        for (; t < tEnd; t++) {
            float w = d_alphas[b*Tt + t];
            float4 v = *(const float4*)(xb + (size_t)t*Hh);
            acc.x = fmaf(w, v.x, acc.x); acc.y = fmaf(w, v.y, acc.y);
            acc.z = fmaf(w, v.z, acc.z); acc.w = fmaf(w, v.w, acc.w);
        }
        float wd = d_dist[b*Tt + j];
        float4 v = *(const float4*)(xb + (size_t)tEnd*Hh);
        acc.x = fmaf(wd, v.x, acc.x); acc.y = fmaf(wd, v.y, acc.y);
        acc.z = fmaf(wd, v.z, acc.z); acc.w = fmaf(wd, v.w, acc.w);
    }

    *(float4*)(outF + ((size_t)b*Tt + j)*Hh + tid*4) = acc;
    *(float4*)(outR + ((size_t)b*Tt + j)*Hh + (Hh - 4 - tid*4)) =
        make_float4(acc.w, acc.z, acc.y, acc.x);
}

// ---------------- launch ----------------
extern "C" void kernel_launch(void* const* d_in, const int* in_sizes, int n_in,
                              void* d_out, int out_size)
{
    const float* x      = (const float*)d_in[0];
    const int*   x_lens = (const int*)  d_in[1];
    const float* pw1_w  = (const float*)d_in[2];
    const float* pw1_b  = (const float*)d_in[3];
    const float* dw_w   = (const float*)d_in[4];
    const float* dw_b   = (const float*)d_in[5];
    const float* ln_g   = (const float*)d_in[6];
    const float* ln_b   = (const float*)d_in[7];
    const float* pw2_w  = (const float*)d_in[8];
    const float* pw2_b  = (const float*)d_in[9];
    const float* lin_w  = (const float*)d_in[10];
    const float* lin_b  = (const float*)d_in[11];
    float* out = (float*)d_out;

    cudaFuncSetAttribute(gemm_glu_mma,   cudaFuncAttributeMaxDynamicSharedMemorySize, SMEM_GEMM);
    cudaFuncSetAttribute(conv_ln_logit2, cudaFuncAttributeMaxDynamicSharedMemorySize, SMEM_CONV);

    presplit_w<<<(1024*128)/256, 256>>>(pw1_w);
    weff_part<<<16, Hh>>>(pw2_w, lin_w);
    weff_sum<<<1, Hh>>>(pw2_b, lin_w, lin_b);
    gemm_glu_mma<<<dim3(8, BT/GM), 256, SMEM_GEMM>>>(x, pw1_b);
    conv_ln_logit2<<<dim3(Tt/CT, Bb), Hh, SMEM_CONV>>>(dw_w, dw_b, ln_g, ln_b, x_lens);
    scan_kernel<<<Bb, 256>>>();
    output_kernel<<<dim3(Tt, Bb), 128>>>(x, out);
}

// round 14
// speedup vs baseline: 1.2989x; 1.1043x over previous
#include <cuda_runtime.h>
#include <cuda_fp16.h>
#include <math.h>
#include <stdint.h>

#define Bb 16
#define Tt 2048
#define Hh 512
#define Kk 15
#define BT (Bb*Tt)

// ---- GEMM tiling ----
#define GM 128
#define GN 128
#define KC 16
#define NCHUNK (Hh/KC)
#define S3 3
#define WPR 12
#define BUFW (GM*WPR)
#define STGB (BUFW*4)
#define OFF_AH 0
#define OFF_AL (S3*BUFW)
#define OFF_BH (2*S3*BUFW)
#define OFF_BL (3*S3*BUFW)
#define SMEM_GEMM (4*S3*BUFW*4)   // 73728 -> 2 blocks/SM

// ---- conv tiling ----
#define CT 32
#define SMEM_CONV ((CT*Hh + 3*Hh)*4)   // 71680

// ---------------- scratch ----------------
__device__ float d_g[(size_t)BT*Hh];
__device__ __align__(16) __half d_wh[1024*Hh];
__device__ __align__(16) __half d_wl[1024*Hh];
__device__ float d_alphas[BT];
__device__ float d_weff[Hh];
__device__ float d_wpart[16*Hh];
__device__ float d_beff;
__device__ int   d_nfires[Bb];
__device__ int   d_fire_t[BT];
__device__ float d_dist[BT];
__device__ float d_remain[BT];
__device__ float d_ptn[Bb];

__device__ __forceinline__ float sigm(float v){ return 1.0f/(1.0f + expf(-v)); }

__device__ __forceinline__ float bfred(float v){
    #pragma unroll
    for (int o = 16; o > 0; o >>= 1) v += __shfl_xor_sync(0xffffffffu, v, o);
    return v;
}

__device__ __forceinline__ void h_split(float v, __half& h, __half& l){
    h = __float2half_rn(v);
    l = __float2half_rn(v - __half2float(h));
}
__device__ __forceinline__ void pack4(const float4& v, uint32_t& hw0, uint32_t& hw1,
                                      uint32_t& lw0, uint32_t& lw1){
    __half hx,lx,hy,ly,hz,lz,hq,lq;
    h_split(v.x,hx,lx); h_split(v.y,hy,ly); h_split(v.z,hz,lz); h_split(v.w,hq,lq);
    __half2 a = __halves2half2(hx,hy); hw0 = *(uint32_t*)&a;
    __half2 b = __halves2half2(hz,hq); hw1 = *(uint32_t*)&b;
    __half2 c = __halves2half2(lx,ly); lw0 = *(uint32_t*)&c;
    __half2 d = __halves2half2(lz,lq); lw1 = *(uint32_t*)&d;
}

__device__ __forceinline__ void mma_f16(float* c, const uint32_t* a, const uint32_t* b){
    asm volatile(
        "mma.sync.aligned.m16n8k16.row.col.f32.f16.f16.f32 "
        "{%0,%1,%2,%3}, {%4,%5,%6,%7}, {%8,%9}, {%0,%1,%2,%3};"
        : "+f"(c[0]), "+f"(c[1]), "+f"(c[2]), "+f"(c[3])
        : "r"(a[0]), "r"(a[1]), "r"(a[2]), "r"(a[3]), "r"(b[0]), "r"(b[1]));
}

__device__ __forceinline__ void ldsm_x4(uint32_t* r, uint32_t addr){
    asm volatile("ldmatrix.sync.aligned.m8n8.x4.shared.b16 {%0,%1,%2,%3}, [%4];"
                 : "=r"(r[0]), "=r"(r[1]), "=r"(r[2]), "=r"(r[3]) : "r"(addr));
}

__device__ __forceinline__ uint32_t smem_u32(const void* p){
    uint32_t a;
    asm("{ .reg .u64 t; cvta.to.shared.u64 t, %1; cvt.u32.u64 %0, t; }" : "=r"(a) : "l"(p));
    return a;
}
__device__ __forceinline__ void cp16(uint32_t dst, const void* src){
    asm volatile("cp.async.cg.shared.global [%0], [%1], 16;"
                 :: "r"(dst), "l"(__cvta_generic_to_global(src)) : "memory");
}
#define CP_COMMIT() asm volatile("cp.async.commit_group;" ::: "memory")
#define CP_WAIT(n)  asm volatile("cp.async.wait_group %0;" :: "n"(n) : "memory")

// ---------------- pre-split: weights only ----------------
__global__ void presplit_w(const float* __restrict__ w)
{
    int i = blockIdx.x*256 + threadIdx.x;
    int nq = i >> 7, kq = i & 127;
    int wr = (nq >> 1) + (nq & 1)*Hh;
    float4 v = *(const float4*)(w + (size_t)wr*Hh + kq*4);
    uint32_t h0,h1,l0,l1;
    pack4(v, h0,h1,l0,l1);
    size_t o = (size_t)nq*128 + kq;
    ((uint2*)d_wh)[o] = make_uint2(h0,h1);
    ((uint2*)d_wl)[o] = make_uint2(l0,l1);
}

// ---------------- weff ----------------
__global__ void weff_part(const float* __restrict__ pw2_w, const float* __restrict__ lin_w)
{
    int t = threadIdx.x, j = blockIdx.x;
    float s = 0.0f;
    #pragma unroll
    for (int o = j*32; o < j*32 + 32; o++)
        s = fmaf(lin_w[o], pw2_w[(size_t)o*Hh + t], s);
    d_wpart[j*Hh + t] = s;
}
__global__ void weff_sum(const float* __restrict__ pw2_b, const float* __restrict__ lin_w,
                         const float* __restrict__ lin_b)
{
    __shared__ float red[16];
    int t = threadIdx.x;
    float s = 0.0f;
    #pragma unroll
    for (int j = 0; j < 16; j++) s += d_wpart[j*Hh + t];
    d_weff[t] = s;
    float p = lin_w[t] * pw2_b[t];
    p = bfred(p);
    if ((t & 31) == 0) red[t >> 5] = p;
    __syncthreads();
    if (t == 0) {
        float bb = lin_b[0];
        #pragma unroll
        for (int i = 0; i < 16; i++) bb += red[i];
        d_beff = bb;
    }
}

// ---------------- kernel 1: fp16x3 mma.sync GEMM + GLU (ldmatrix fragments) ----------------
__global__ void __launch_bounds__(256, 2)
gemm_glu_mma(const float* __restrict__ x, const float* __restrict__ bias)
{
    extern __shared__ uint32_t smg[];
    const uint32_t sm0 = smem_u32(smg);

    const int tid  = threadIdx.x;
    const int wid  = tid >> 5;
    const int lane = tid & 31;
    const int gid  = lane >> 2;
    const int tig  = lane & 3;
    const int mB = blockIdx.y * GM;
    const int nB = blockIdx.x * GN;
    const int cB = nB >> 1;
    const int mw = (wid & 3) * 32;
    const int nw = (wid >> 2) * 64;

    // ldmatrix lane address offsets (bytes within a stage buffer)
    const int l7 = lane & 7;
    const uint32_t aByte = (uint32_t)(mw + l7 + ((lane & 8) ? 8 : 0))*WPR*4
                         + ((lane & 16) ? 16u : 0u);
    const uint32_t bByte = (uint32_t)(nw + l7 + ((lane & 16) ? 8 : 0))*WPR*4
                         + ((lane & 8) ? 16u : 0u);

    // producer mapping
    const int r_  = tid >> 1;
    const int hq_ = tid & 1;
    const uint32_t dOff = (uint32_t)(r_*WPR)*4 + hq_*16;
    const float*  gax = x + (size_t)(mB + r_)*Hh + hq_*8;
    const size_t  gb0 = ((size_t)(nB + r_)*Hh)*2 + hq_*16;

    #define ISSUEB(c) do { \
        const int st_ = (c) % S3; \
        const size_t kb_ = (size_t)(c)*KC*2; \
        cp16(sm0 + (OFF_BH*4) + st_*STGB + dOff, (const char*)d_wh + gb0 + kb_); \
        cp16(sm0 + (OFF_BL*4) + st_*STGB + dOff, (const char*)d_wl + gb0 + kb_); \
        CP_COMMIT(); \
    } while(0)

    float4 xa0, xa1;
    #define LDGA(c) do { \
        xa0 = *(const float4*)(gax + (size_t)(c)*KC); \
        xa1 = *(const float4*)(gax + (size_t)(c)*KC + 4); \
    } while(0)

    #define STSA(c) do { \
        const int st_ = (c) % S3; \
        uint32_t h0,h1,h2,h3,l0,l1,l2,l3; \
        pack4(xa0, h0,h1,l0,l1); \
        pack4(xa1, h2,h3,l2,l3); \
        *(uint4*)((char*)smg + (OFF_AH*4) + st_*STGB + dOff) = make_uint4(h0,h1,h2,h3); \
        *(uint4*)((char*)smg + (OFF_AL*4) + st_*STGB + dOff) = make_uint4(l0,l1,l2,l3); \
    } while(0)

    float acc[2][8][4];
    #pragma unroll
    for (int mt = 0; mt < 2; mt++)
        #pragma unroll
        for (int nt = 0; nt < 8; nt++)
            #pragma unroll
            for (int e = 0; e < 4; e++) acc[mt][nt][e] = 0.0f;

    #define COMPUTE(buf) do { \
        const uint32_t aAH = sm0 + (OFF_AH*4) + (buf)*STGB + aByte; \
        const uint32_t aAL = sm0 + (OFF_AL*4) + (buf)*STGB + aByte; \
        const uint32_t bBH = sm0 + (OFF_BH*4) + (buf)*STGB + bByte; \
        const uint32_t bBL = sm0 + (OFF_BL*4) + (buf)*STGB + bByte; \
        uint32_t ah[2][4], al[2][4], bh[8][2], bl[8][2]; \
        ldsm_x4(ah[0], aAH); \
        ldsm_x4(ah[1], aAH + 16*WPR*4); \
        ldsm_x4(al[0], aAL); \
        ldsm_x4(al[1], aAL + 16*WPR*4); \
        _Pragma("unroll") \
        for (int p = 0; p < 4; p++) { \
            uint32_t t4[4]; \
            ldsm_x4(t4, bBH + p*(16*WPR*4)); \
            bh[2*p][0] = t4[0]; bh[2*p][1] = t4[1]; \
            bh[2*p+1][0] = t4[2]; bh[2*p+1][1] = t4[3]; \
        } \
        _Pragma("unroll") \
        for (int p = 0; p < 4; p++) { \
            uint32_t t4[4]; \
            ldsm_x4(t4, bBL + p*(16*WPR*4)); \
            bl[2*p][0] = t4[0]; bl[2*p][1] = t4[1]; \
            bl[2*p+1][0] = t4[2]; bl[2*p+1][1] = t4[3]; \
        } \
        _Pragma("unroll") \
        for (int nt = 0; nt < 8; nt++) { \
            mma_f16(acc[0][nt], ah[0], bh[nt]); \
            mma_f16(acc[1][nt], ah[1], bh[nt]); \
        } \
        _Pragma("unroll") \
        for (int nt = 0; nt < 8; nt++) { \
            mma_f16(acc[0][nt], ah[0], bl[nt]); \
            mma_f16(acc[1][nt], ah[1], bl[nt]); \
        } \
        _Pragma("unroll") \
        for (int nt = 0; nt < 8; nt++) { \
            mma_f16(acc[0][nt], al[0], bh[nt]); \
            mma_f16(acc[1][nt], al[1], bh[nt]); \
        } \
    } while(0)

    ISSUEB(0);
    ISSUEB(1);
    LDGA(0);
    STSA(0);

    #pragma unroll 1
    for (int c = 0; c < NCHUNK; c++) {
        if (c + 1 < NCHUNK) LDGA(c + 1);
        if (c < NCHUNK - 1) { CP_WAIT(1); } else { CP_WAIT(0); }
        __syncthreads();
        COMPUTE(c % S3);
        if (c + 2 < NCHUNK) ISSUEB(c + 2);
        __syncthreads();
        if (c + 1 < NCHUNK) STSA(c + 1);
    }

    // ---- epilogue: GLU on (even,odd) col pairs -> d_g ----
    #pragma unroll
    for (int nt = 0; nt < 8; nt++) {
        const int ch = cB + (nw >> 1) + nt*4 + tig;
        const float bv = bias[ch];
        const float bg = bias[Hh + ch];
        #pragma unroll
        for (int mt = 0; mt < 2; mt++) {
            const int m0 = mB + mw + mt*16 + gid;
            float g0 = (acc[mt][nt][0] + bv) * sigm(acc[mt][nt][1] + bg);
            float g2 = (acc[mt][nt][2] + bv) * sigm(acc[mt][nt][3] + bg);
            d_g[(size_t)m0*Hh + ch]       = g0;
            d_g[(size_t)(m0 + 8)*Hh + ch] = g2;
        }
    }
}

// ---------------- kernel 2: conv + LN + swish -> alphas ----------------
__global__ void __launch_bounds__(512, 2)
conv_ln_logit2(const float* __restrict__ dw_w, const float* __restrict__ dw_b,
               const float* __restrict__ ln_g, const float* __restrict__ ln_b,
               const int* __restrict__ x_lens)
{
    extern __shared__ float smc[];
    float* cs = smc;
    float* pg = smc + CT*Hh;
    float* pb = pg + Hh;
    float* pw = pb + Hh;

    const int ch = threadIdx.x;
    const int b  = blockIdx.y;
    const int t0 = blockIdx.x * CT;
    const int lane = ch & 31;
    const int wrp  = ch >> 5;

    {
        float wk[15];
        #pragma unroll
        for (int k = 0; k < 15; k++) wk[k] = dw_w[ch*Kk + k];
        const float bias = dw_b[ch];
        const float* gb = d_g + (size_t)b*Tt*Hh + ch;

        float win[15];
        #pragma unroll
        for (int k = 0; k < 14; k++) {
            int tg = t0 - 14 + k;
            win[k] = (tg >= 0) ? gb[(size_t)tg*Hh] : 0.0f;
        }
        #pragma unroll
        for (int t = 0; t < CT; t++) {
            win[(t+14)%15] = gb[(size_t)(t0 + t)*Hh];
            float c = bias;
            #pragma unroll
            for (int k = 0; k < 15; k++) c = fmaf(win[(t+k)%15], wk[k], c);
            cs[t*Hh + ch] = c;
        }
        pg[ch] = ln_g[ch];
        pb[ch] = ln_b[ch];
        pw[ch] = d_weff[ch];
    }
    __syncthreads();

    const int len  = x_lens[b];
    const float beff = d_beff;
    #pragma unroll
    for (int rep = 0; rep < 2; rep++) {
        const int t = wrp*2 + rep;
        const float* cr = cs + t*Hh + lane*4;
        float4 c4[4];
        #pragma unroll
        for (int q = 0; q < 4; q++) c4[q] = *(const float4*)(cr + q*128);

        float s1 = 0.0f, s2 = 0.0f;
        #pragma unroll
        for (int q = 0; q < 4; q++) {
            const float* cp = (const float*)&c4[q];
            #pragma unroll
            for (int e = 0; e < 4; e++) { s1 += cp[e]; s2 = fmaf(cp[e], cp[e], s2); }
        }
        s1 = bfred(s1);
        s2 = bfred(s2);
        float mean = s1 * (1.0f/512.0f);
        float var  = s2 * (1.0f/512.0f) - mean*mean;
        float rstd = rsqrtf(var + 1e-5f);

        float dot = 0.0f;
        #pragma unroll
        for (int q = 0; q < 4; q++) {
            float4 g4 = *(const float4*)(pg + lane*4 + q*128);
            float4 b4 = *(const float4*)(pb + lane*4 + q*128);
            float4 w4 = *(const float4*)(pw + lane*4 + q*128);
            const float* cp = (const float*)&c4[q];
            const float* gp = (const float*)&g4;
            const float* bp = (const float*)&b4;
            const float* wp = (const float*)&w4;
            #pragma unroll
            for (int e = 0; e < 4; e++) {
                float y  = (cp[e] - mean) * rstd * gp[e] + bp[e];
                float sw = y * sigm(y);
                dot = fmaf(sw, wp[e], dot);
            }
        }
        dot = bfred(dot);
        if (lane == 0) {
            int tg = t0 + t;
            d_alphas[b*Tt + tg] = (tg < len) ? sigm(dot + beff) : 0.0f;
        }
    }
}

// ---------------- kernel 3: per-batch serial CIF scan ----------------
__global__ void scan_kernel()
{
    __shared__ float sa[Tt];
    const int b = blockIdx.x;
    for (int i = threadIdx.x; i < Tt; i += blockDim.x) sa[i] = d_alphas[b*Tt + i];
    __syncthreads();
    if (threadIdx.x == 0) {
        float integ = 0.0f, psum = 0.0f;
        int j = 0;
        for (int t = 0; t < Tt; t++) {
            float a = sa[t];
            psum += a;
            float tt = integ + a;
            bool fire = (tt >= 1.0f);
            if (fire) {
                float dist = 1.0f - integ;
                d_fire_t[b*Tt + j] = t;
                d_dist  [b*Tt + j] = dist;
                d_remain[b*Tt + j] = a - dist;
                j++;
            }
            integ = fire ? (tt - 1.0f) : tt;
        }
        d_nfires[b] = j;
        d_ptn[b] = psum;
    }
}

// ---------------- kernel 4: write all outputs ----------------
__launch_bounds__(128)
__global__ void output_kernel(const float* __restrict__ x, float* __restrict__ out)
{
    const int b   = blockIdx.y;
    const int j   = blockIdx.x;
    const int tid = threadIdx.x;
    float* outF = out;
    float* outP = out + (size_t)Bb*Tt*Hh;
    float* outR = outP + Bb;

    if (j == 0 && tid == 0) outP[b] = d_ptn[b];

    float4 acc = make_float4(0.0f, 0.0f, 0.0f, 0.0f);
    const int nf = d_nfires[b];

    if (j < nf) {
        const float* xb = x + (size_t)b*Tt*Hh + tid*4;
        const int tEnd = d_fire_t[b*Tt + j];
        int t;
        if (j > 0) {
            int   tPrev = d_fire_t[b*Tt + j - 1];
            float wl    = d_remain[b*Tt + j - 1];
            float4 v = *(const float4*)(xb + (size_t)tPrev*Hh);
            acc.x = wl*v.x; acc.y = wl*v.y; acc.z = wl*v.z; acc.w = wl*v.w;
            t = tPrev + 1;
        } else {
            t = 0;
        }
        for (; t < tEnd; t++) {
            float w = d_alphas[b*Tt + t];
            float4 v = *(const float4*)(xb + (size_t)t*Hh);
            acc.x = fmaf(w, v.x, acc.x); acc.y = fmaf(w, v.y, acc.y);
            acc.z = fmaf(w, v.z, acc.z); acc.w = fmaf(w, v.w, acc.w);
        }
        float wd = d_dist[b*Tt + j];
        float4 v = *(const float4*)(xb + (size_t)tEnd*Hh);
        acc.x = fmaf(wd, v.x, acc.x); acc.y = fmaf(wd, v.y, acc.y);
        acc.z = fmaf(wd, v.z, acc.z); acc.w = fmaf(wd, v.w, acc.w);
    }

    *(float4*)(outF + ((size_t)b*Tt + j)*Hh + tid*4) = acc;
    *(float4*)(outR + ((size_t)b*Tt + j)*Hh + (Hh - 4 - tid*4)) =
        make_float4(acc.w, acc.z, acc.y, acc.x);
}

// ---------------- launch ----------------
extern "C" void kernel_launch(void* const* d_in, const int* in_sizes, int n_in,
                              void* d_out, int out_size)
{
    const float* x      = (const float*)d_in[0];
    const int*   x_lens = (const int*)  d_in[1];
    const float* pw1_w  = (const float*)d_in[2];
    const float* pw1_b  = (const float*)d_in[3];
    const float* dw_w   = (const float*)d_in[4];
    const float* dw_b   = (const float*)d_in[5];
    const float* ln_g   = (const float*)d_in[6];
    const float* ln_b   = (const float*)d_in[7];
    const float* pw2_w  = (const float*)d_in[8];
    const float* pw2_b  = (const float*)d_in[9];
    const float* lin_w  = (const float*)d_in[10];
    const float* lin_b  = (const float*)d_in[11];
    float* out = (float*)d_out;

    cudaFuncSetAttribute(gemm_glu_mma,   cudaFuncAttributeMaxDynamicSharedMemorySize, SMEM_GEMM);
    cudaFuncSetAttribute(conv_ln_logit2, cudaFuncAttributeMaxDynamicSharedMemorySize, SMEM_CONV);

    presplit_w<<<(1024*128)/256, 256>>>(pw1_w);
    weff_part<<<16, Hh>>>(pw2_w, lin_w);
    weff_sum<<<1, Hh>>>(pw2_b, lin_w, lin_b);
    gemm_glu_mma<<<dim3(8, BT/GM), 256, SMEM_GEMM>>>(x, pw1_b);
    conv_ln_logit2<<<dim3(Tt/CT, Bb), Hh, SMEM_CONV>>>(dw_w, dw_b, ln_g, ln_b, x_lens);
    scan_kernel<<<Bb, 256>>>();
    output_kernel<<<dim3(Tt, Bb), 128>>>(x, out);
}

// round 15
// speedup vs baseline: 1.3375x; 1.0298x over previous
#include <cuda_runtime.h>
#include <cuda_fp16.h>
#include <math.h>
#include <stdint.h>

#define Bb 16
#define Tt 2048
#define Hh 512
#define Kk 15
#define BT (Bb*Tt)

// ---- GEMM tiling ----
#define GM 128
#define GN 128
#define KC 32                 // K per chunk (two m16n8k16 steps)
#define NCHUNK (Hh/KC)        // 16
#define WPR 20                // words per row (16 data + 4 pad): LDSM conflict-free at 80B pitch
#define BUFW (GM*WPR)         // 2560 words per operand-stage
#define STGB (BUFW*4)         // 10240 bytes
#define OFF_AH 0
#define OFF_AL (2*BUFW)
#define OFF_BH (4*BUFW)
#define OFF_BL (6*BUFW)
#define SMEM_GEMM (8*BUFW*4)  // 81920 -> 2 blocks/SM

// ---- conv tiling ----
#define CT 32
#define SMEM_CONV ((CT*Hh + 3*Hh)*4)   // 71680

// ---------------- scratch ----------------
__device__ float d_g[(size_t)BT*Hh];
__device__ __align__(16) __half d_wh[1024*Hh];
__device__ __align__(16) __half d_wl[1024*Hh];
__device__ float d_alphas[BT];
__device__ float d_weff[Hh];
__device__ float d_wpart[16*Hh];
__device__ float d_beff;
__device__ int   d_nfires[Bb];
__device__ int   d_fire_t[BT];
__device__ float d_dist[BT];
__device__ float d_remain[BT];
__device__ float d_ptn[Bb];

__device__ __forceinline__ float sigm(float v){ return 1.0f/(1.0f + expf(-v)); }

__device__ __forceinline__ float bfred(float v){
    #pragma unroll
    for (int o = 16; o > 0; o >>= 1) v += __shfl_xor_sync(0xffffffffu, v, o);
    return v;
}

__device__ __forceinline__ void h_split(float v, __half& h, __half& l){
    h = __float2half_rn(v);
    l = __float2half_rn(v - __half2float(h));
}
__device__ __forceinline__ void pack4(const float4& v, uint32_t& hw0, uint32_t& hw1,
                                      uint32_t& lw0, uint32_t& lw1){
    __half hx,lx,hy,ly,hz,lz,hq,lq;
    h_split(v.x,hx,lx); h_split(v.y,hy,ly); h_split(v.z,hz,lz); h_split(v.w,hq,lq);
    __half2 a = __halves2half2(hx,hy); hw0 = *(uint32_t*)&a;
    __half2 b = __halves2half2(hz,hq); hw1 = *(uint32_t*)&b;
    __half2 c = __halves2half2(lx,ly); lw0 = *(uint32_t*)&c;
    __half2 d = __halves2half2(lz,lq); lw1 = *(uint32_t*)&d;
}

__device__ __forceinline__ void mma_f16(float* c, const uint32_t* a, const uint32_t* b){
    asm volatile(
        "mma.sync.aligned.m16n8k16.row.col.f32.f16.f16.f32 "
        "{%0,%1,%2,%3}, {%4,%5,%6,%7}, {%8,%9}, {%0,%1,%2,%3};"
        : "+f"(c[0]), "+f"(c[1]), "+f"(c[2]), "+f"(c[3])
        : "r"(a[0]), "r"(a[1]), "r"(a[2]), "r"(a[3]), "r"(b[0]), "r"(b[1]));
}

__device__ __forceinline__ void ldsm_x4(uint32_t* r, uint32_t addr){
    asm volatile("ldmatrix.sync.aligned.m8n8.x4.shared.b16 {%0,%1,%2,%3}, [%4];"
                 : "=r"(r[0]), "=r"(r[1]), "=r"(r[2]), "=r"(r[3]) : "r"(addr));
}

__device__ __forceinline__ uint32_t smem_u32(const void* p){
    uint32_t a;
    asm("{ .reg .u64 t; cvta.to.shared.u64 t, %1; cvt.u32.u64 %0, t; }" : "=r"(a) : "l"(p));
    return a;
}
__device__ __forceinline__ void cp16(uint32_t dst, const void* src){
    asm volatile("cp.async.cg.shared.global [%0], [%1], 16;"
                 :: "r"(dst), "l"(__cvta_generic_to_global(src)) : "memory");
}
#define CP_COMMIT() asm volatile("cp.async.commit_group;" ::: "memory")
#define CP_WAIT(n)  asm volatile("cp.async.wait_group %0;" :: "n"(n) : "memory")

// ---------------- pre-split: weights only ----------------
__global__ void presplit_w(const float* __restrict__ w)
{
    int i = blockIdx.x*256 + threadIdx.x;
    int nq = i >> 7, kq = i & 127;
    int wr = (nq >> 1) + (nq & 1)*Hh;
    float4 v = *(const float4*)(w + (size_t)wr*Hh + kq*4);
    uint32_t h0,h1,l0,l1;
    pack4(v, h0,h1,l0,l1);
    size_t o = (size_t)nq*128 + kq;
    ((uint2*)d_wh)[o] = make_uint2(h0,h1);
    ((uint2*)d_wl)[o] = make_uint2(l0,l1);
}

// ---------------- weff ----------------
__global__ void weff_part(const float* __restrict__ pw2_w, const float* __restrict__ lin_w)
{
    int t = threadIdx.x, j = blockIdx.x;
    float s = 0.0f;
    #pragma unroll
    for (int o = j*32; o < j*32 + 32; o++)
        s = fmaf(lin_w[o], pw2_w[(size_t)o*Hh + t], s);
    d_wpart[j*Hh + t] = s;
}
__global__ void weff_sum(const float* __restrict__ pw2_b, const float* __restrict__ lin_w,
                         const float* __restrict__ lin_b)
{
    __shared__ float red[16];
    int t = threadIdx.x;
    float s = 0.0f;
    #pragma unroll
    for (int j = 0; j < 16; j++) s += d_wpart[j*Hh + t];
    d_weff[t] = s;
    float p = lin_w[t] * pw2_b[t];
    p = bfred(p);
    if ((t & 31) == 0) red[t >> 5] = p;
    __syncthreads();
    if (t == 0) {
        float bb = lin_b[0];
        #pragma unroll
        for (int i = 0; i < 16; i++) bb += red[i];
        d_beff = bb;
    }
}

// ---------------- kernel 1: fp16x3 mma.sync GEMM + GLU (KC=32, 1 barrier/chunk) ----------------
__global__ void __launch_bounds__(256, 2)
gemm_glu_mma(const float* __restrict__ x, const float* __restrict__ bias)
{
    extern __shared__ uint32_t smg[];
    const uint32_t sm0 = smem_u32(smg);

    const int tid  = threadIdx.x;
    const int wid  = tid >> 5;
    const int lane = tid & 31;
    const int gid  = lane >> 2;
    const int tig  = lane & 3;
    const int mB = blockIdx.y * GM;
    const int nB = blockIdx.x * GN;
    const int cB = nB >> 1;
    const int mw = (wid & 3) * 32;
    const int nw = (wid >> 2) * 64;

    // ldmatrix lane byte offsets within a stage buffer (80B row pitch)
    const int l7 = lane & 7;
    const uint32_t aByte = (uint32_t)(mw + l7 + ((lane & 8) ? 8 : 0))*(WPR*4)
                         + ((lane & 16) ? 16u : 0u);
    const uint32_t bByte = (uint32_t)(nw + l7 + ((lane & 16) ? 8 : 0))*(WPR*4)
                         + ((lane & 8) ? 16u : 0u);

    // A producer: thread covers row r_=tid>>1, k-half hq_ (16 f32)
    const int rA  = tid >> 1;
    const int hqA = tid & 1;
    const uint32_t dOffA = (uint32_t)rA*(WPR*4) + hqA*32;
    const float*  gax = x + (size_t)(mB + rA)*Hh + hqA*16;

    // B producer: thread covers rows rB, rB+64; piece pB (16B of the 64B chunk-row)
    const int rB = tid >> 2;
    const int pB = tid & 3;
    const uint32_t dOffB0 = (uint32_t)rB*(WPR*4) + pB*16;
    const uint32_t dOffB1 = (uint32_t)(rB + 64)*(WPR*4) + pB*16;
    const size_t  gbB0 = ((size_t)(nB + rB)*Hh)*2 + pB*16;
    const size_t  gbB1 = ((size_t)(nB + rB + 64)*Hh)*2 + pB*16;

    #define ISSUEB(c) do { \
        const int st_ = (c) & 1; \
        const size_t kb_ = (size_t)(c)*KC*2; \
        cp16(sm0 + (OFF_BH*4) + st_*STGB + dOffB0, (const char*)d_wh + gbB0 + kb_); \
        cp16(sm0 + (OFF_BH*4) + st_*STGB + dOffB1, (const char*)d_wh + gbB1 + kb_); \
        cp16(sm0 + (OFF_BL*4) + st_*STGB + dOffB0, (const char*)d_wl + gbB0 + kb_); \
        cp16(sm0 + (OFF_BL*4) + st_*STGB + dOffB1, (const char*)d_wl + gbB1 + kb_); \
        CP_COMMIT(); \
    } while(0)

    float4 xa0, xa1, xa2, xa3;
    #define LDGA(c) do { \
        const float* gp_ = gax + (size_t)(c)*KC; \
        xa0 = *(const float4*)(gp_);      xa1 = *(const float4*)(gp_ + 4); \
        xa2 = *(const float4*)(gp_ + 8);  xa3 = *(const float4*)(gp_ + 12); \
    } while(0)

    #define STSA(c) do { \
        const int st_ = (c) & 1; \
        uint32_t h0,h1,h2,h3,l0,l1,l2,l3; \
        pack4(xa0, h0,h1,l0,l1); \
        pack4(xa1, h2,h3,l2,l3); \
        *(uint4*)((char*)smg + (OFF_AH*4) + st_*STGB + dOffA) = make_uint4(h0,h1,h2,h3); \
        *(uint4*)((char*)smg + (OFF_AL*4) + st_*STGB + dOffA) = make_uint4(l0,l1,l2,l3); \
        pack4(xa2, h0,h1,l0,l1); \
        pack4(xa3, h2,h3,l2,l3); \
        *(uint4*)((char*)smg + (OFF_AH*4) + st_*STGB + dOffA + 16) = make_uint4(h0,h1,h2,h3); \
        *(uint4*)((char*)smg + (OFF_AL*4) + st_*STGB + dOffA + 16) = make_uint4(l0,l1,l2,l3); \
    } while(0)

    float acc[2][8][4];
    #pragma unroll
    for (int mt = 0; mt < 2; mt++)
        #pragma unroll
        for (int nt = 0; nt < 8; nt++)
            #pragma unroll
            for (int e = 0; e < 4; e++) acc[mt][nt][e] = 0.0f;

    // two m16n8k16 steps per chunk (step byte offset = s*32 within row)
    #define COMPUTE(buf) do { \
        _Pragma("unroll") \
        for (int s = 0; s < 2; s++) { \
            const uint32_t so = (buf)*STGB + s*32u; \
            const uint32_t aAH = sm0 + (OFF_AH*4) + so + aByte; \
            const uint32_t aAL = sm0 + (OFF_AL*4) + so + aByte; \
            const uint32_t bBH = sm0 + (OFF_BH*4) + so + bByte; \
            const uint32_t bBL = sm0 + (OFF_BL*4) + so + bByte; \
            uint32_t ah[2][4], al[2][4], bh[8][2], bl[8][2]; \
            ldsm_x4(ah[0], aAH); \
            ldsm_x4(ah[1], aAH + 16*(WPR*4)); \
            ldsm_x4(al[0], aAL); \
            ldsm_x4(al[1], aAL + 16*(WPR*4)); \
            _Pragma("unroll") \
            for (int p = 0; p < 4; p++) { \
                uint32_t t4[4]; \
                ldsm_x4(t4, bBH + p*(16*(WPR*4))); \
                bh[2*p][0] = t4[0]; bh[2*p][1] = t4[1]; \
                bh[2*p+1][0] = t4[2]; bh[2*p+1][1] = t4[3]; \
            } \
            _Pragma("unroll") \
            for (int p = 0; p < 4; p++) { \
                uint32_t t4[4]; \
                ldsm_x4(t4, bBL + p*(16*(WPR*4))); \
                bl[2*p][0] = t4[0]; bl[2*p][1] = t4[1]; \
                bl[2*p+1][0] = t4[2]; bl[2*p+1][1] = t4[3]; \
            } \
            _Pragma("unroll") \
            for (int nt = 0; nt < 8; nt++) { \
                mma_f16(acc[0][nt], ah[0], bh[nt]); \
                mma_f16(acc[1][nt], ah[1], bh[nt]); \
            } \
            _Pragma("unroll") \
            for (int nt = 0; nt < 8; nt++) { \
                mma_f16(acc[0][nt], ah[0], bl[nt]); \
                mma_f16(acc[1][nt], ah[1], bl[nt]); \
            } \
            _Pragma("unroll") \
            for (int nt = 0; nt < 8; nt++) { \
                mma_f16(acc[0][nt], al[0], bh[nt]); \
                mma_f16(acc[1][nt], al[1], bh[nt]); \
            } \
        } \
    } while(0)

    // prologue
    ISSUEB(0);
    LDGA(0);
    STSA(0);

    #pragma unroll 1
    for (int c = 0; c < NCHUNK; c++) {
        CP_WAIT(0);
        __syncthreads();                 // stage c&1 ready (A stored last iter, B arrived)
        if (c + 1 < NCHUNK) ISSUEB(c + 1);
        COMPUTE(c & 1);
        if (c + 1 < NCHUNK) {
            LDGA(c + 1);
            STSA(c + 1);                 // writes stage (c+1)&1: readers all passed this iter's barrier
        }
    }

    // ---- epilogue: GLU on (even,odd) col pairs -> d_g ----
    #pragma unroll
    for (int nt = 0; nt < 8; nt++) {
        const int ch = cB + (nw >> 1) + nt*4 + tig;
        const float bv = bias[ch];
        const float bg = bias[Hh + ch];
        #pragma unroll
        for (int mt = 0; mt < 2; mt++) {
            const int m0 = mB + mw + mt*16 + gid;
            float g0 = (acc[mt][nt][0] + bv) * sigm(acc[mt][nt][1] + bg);
            float g2 = (acc[mt][nt][2] + bv) * sigm(acc[mt][nt][3] + bg);
            d_g[(size_t)m0*Hh + ch]       = g0;
            d_g[(size_t)(m0 + 8)*Hh + ch] = g2;
        }
    }
}

// ---------------- kernel 2: conv + LN + swish -> alphas ----------------
__global__ void __launch_bounds__(512, 2)
conv_ln_logit2(const float* __restrict__ dw_w, const float* __restrict__ dw_b,
               const float* __restrict__ ln_g, const float* __restrict__ ln_b,
               const int* __restrict__ x_lens)
{
    extern __shared__ float smc[];
    float* cs = smc;
    float* pg = smc + CT*Hh;
    float* pb = pg + Hh;
    float* pw = pb + Hh;

    const int ch = threadIdx.x;
    const int b  = blockIdx.y;
    const int t0 = blockIdx.x * CT;
    const int lane = ch & 31;
    const int wrp  = ch >> 5;

    {
        float wk[15];
        #pragma unroll
        for (int k = 0; k < 15; k++) wk[k] = dw_w[ch*Kk + k];
        const float bias = dw_b[ch];
        const float* gb = d_g + (size_t)b*Tt*Hh + ch;

        float win[15];
        #pragma unroll
        for (int k = 0; k < 14; k++) {
            int tg = t0 - 14 + k;
            win[k] = (tg >= 0) ? gb[(size_t)tg*Hh] : 0.0f;
        }
        #pragma unroll
        for (int t = 0; t < CT; t++) {
            win[(t+14)%15] = gb[(size_t)(t0 + t)*Hh];
            float c = bias;
            #pragma unroll
            for (int k = 0; k < 15; k++) c = fmaf(win[(t+k)%15], wk[k], c);
            cs[t*Hh + ch] = c;
        }
        pg[ch] = ln_g[ch];
        pb[ch] = ln_b[ch];
        pw[ch] = d_weff[ch];
    }
    __syncthreads();

    const int len  = x_lens[b];
    const float beff = d_beff;
    #pragma unroll
    for (int rep = 0; rep < 2; rep++) {
        const int t = wrp*2 + rep;
        const float* cr = cs + t*Hh + lane*4;
        float4 c4[4];
        #pragma unroll
        for (int q = 0; q < 4; q++) c4[q] = *(const float4*)(cr + q*128);

        float s1 = 0.0f, s2 = 0.0f;
        #pragma unroll
        for (int q = 0; q < 4; q++) {
            const float* cp = (const float*)&c4[q];
            #pragma unroll
            for (int e = 0; e < 4; e++) { s1 += cp[e]; s2 = fmaf(cp[e], cp[e], s2); }
        }
        s1 = bfred(s1);
        s2 = bfred(s2);
        float mean = s1 * (1.0f/512.0f);
        float var  = s2 * (1.0f/512.0f) - mean*mean;
        float rstd = rsqrtf(var + 1e-5f);

        float dot = 0.0f;
        #pragma unroll
        for (int q = 0; q < 4; q++) {
            float4 g4 = *(const float4*)(pg + lane*4 + q*128);
            float4 b4 = *(const float4*)(pb + lane*4 + q*128);
            float4 w4 = *(const float4*)(pw + lane*4 + q*128);
            const float* cp = (const float*)&c4[q];
            const float* gp = (const float*)&g4;
            const float* bp = (const float*)&b4;
            const float* wp = (const float*)&w4;
            #pragma unroll
            for (int e = 0; e < 4; e++) {
                float y  = (cp[e] - mean) * rstd * gp[e] + bp[e];
                float sw = y * sigm(y);
                dot = fmaf(sw, wp[e], dot);
            }
        }
        dot = bfred(dot);
        if (lane == 0) {
            int tg = t0 + t;
            d_alphas[b*Tt + tg] = (tg < len) ? sigm(dot + beff) : 0.0f;
        }
    }
}

// ---------------- kernel 3: per-batch serial CIF scan ----------------
__global__ void scan_kernel()
{
    __shared__ float sa[Tt];
    const int b = blockIdx.x;
    for (int i = threadIdx.x; i < Tt; i += blockDim.x) sa[i] = d_alphas[b*Tt + i];
    __syncthreads();
    if (threadIdx.x == 0) {
        float integ = 0.0f, psum = 0.0f;
        int j = 0;
        for (int t = 0; t < Tt; t++) {
            float a = sa[t];
            psum += a;
            float tt = integ + a;
            bool fire = (tt >= 1.0f);
            if (fire) {
                float dist = 1.0f - integ;
                d_fire_t[b*Tt + j] = t;
                d_dist  [b*Tt + j] = dist;
                d_remain[b*Tt + j] = a - dist;
                j++;
            }
            integ = fire ? (tt - 1.0f) : tt;
        }
        d_nfires[b] = j;
        d_ptn[b] = psum;
    }
}

// ---------------- kernel 4: write all outputs ----------------
__launch_bounds__(128)
__global__ void output_kernel(const float* __restrict__ x, float* __restrict__ out)
{
    const int b   = blockIdx.y;
    const int j   = blockIdx.x;
    const int tid = threadIdx.x;
    float* outF = out;
    float* outP = out + (size_t)Bb*Tt*Hh;
    float* outR = outP + Bb;

    if (j == 0 && tid == 0) outP[b] = d_ptn[b];

    float4 acc = make_float4(0.0f, 0.0f, 0.0f, 0.0f);
    const int nf = d_nfires[b];

    if (j < nf) {
        const float* xb = x + (size_t)b*Tt*Hh + tid*4;
        const int tEnd = d_fire_t[b*Tt + j];
        int t;
        if (j > 0) {
            int   tPrev = d_fire_t[b*Tt + j - 1];
            float wl    = d_remain[b*Tt + j - 1];
            float4 v = *(const float4*)(xb + (size_t)tPrev*Hh);
            acc.x = wl*v.x; acc.y = wl*v.y; acc.z = wl*v.z; acc.w = wl*v.w;
            t = tPrev + 1;
        } else {
            t = 0;
        }
        for (; t < tEnd; t++) {
            float w = d_alphas[b*Tt + t];
            float4 v = *(const float4*)(xb + (size_t)t*Hh);
            acc.x = fmaf(w, v.x, acc.x); acc.y = fmaf(w, v.y, acc.y);
            acc.z = fmaf(w, v.z, acc.z); acc.w = fmaf(w, v.w, acc.w);
        }
        float wd = d_dist[b*Tt + j];
        float4 v = *(const float4*)(xb + (size_t)tEnd*Hh);
        acc.x = fmaf(wd, v.x, acc.x); acc.y = fmaf(wd, v.y, acc.y);
        acc.z = fmaf(wd, v.z, acc.z); acc.w = fmaf(wd, v.w, acc.w);
    }

    *(float4*)(outF + ((size_t)b*Tt + j)*Hh + tid*4) = acc;
    *(float4*)(outR + ((size_t)b*Tt + j)*Hh + (Hh - 4 - tid*4)) =
        make_float4(acc.w, acc.z, acc.y, acc.x);
}

// ---------------- launch ----------------
extern "C" void kernel_launch(void* const* d_in, const int* in_sizes, int n_in,
                              void* d_out, int out_size)
{
    const float* x      = (const float*)d_in[0];
    const int*   x_lens = (const int*)  d_in[1];
    const float* pw1_w  = (const float*)d_in[2];
    const float* pw1_b  = (const float*)d_in[3];
    const float* dw_w   = (const float*)d_in[4];
    const float* dw_b   = (const float*)d_in[5];
    const float* ln_g   = (const float*)d_in[6];
    const float* ln_b   = (const float*)d_in[7];
    const float* pw2_w  = (const float*)d_in[8];
    const float* pw2_b  = (const float*)d_in[9];
    const float* lin_w  = (const float*)d_in[10];
    const float* lin_b  = (const float*)d_in[11];
    float* out = (float*)d_out;

    cudaFuncSetAttribute(gemm_glu_mma,   cudaFuncAttributeMaxDynamicSharedMemorySize, SMEM_GEMM);
    cudaFuncSetAttribute(conv_ln_logit2, cudaFuncAttributeMaxDynamicSharedMemorySize, SMEM_CONV);

    presplit_w<<<(1024*128)/256, 256>>>(pw1_w);
    weff_part<<<16, Hh>>>(pw2_w, lin_w);
    weff_sum<<<1, Hh>>>(pw2_b, lin_w, lin_b);
    gemm_glu_mma<<<dim3(8, BT/GM), 256, SMEM_GEMM>>>(x, pw1_b);
    conv_ln_logit2<<<dim3(Tt/CT, Bb), Hh, SMEM_CONV>>>(dw_w, dw_b, ln_g, ln_b, x_lens);
    scan_kernel<<<Bb, 256>>>();
    output_kernel<<<dim3(Tt, Bb), 128>>>(x, out);
}